// round 13
// baseline (speedup 1.0000x reference)
#include <cuda_runtime.h>
#include <cuda_fp16.h>
#include <math.h>
#include <stdint.h>

#define NROWS 4096
#define DIN   4096
#define DLAT  32768
#define K_TOP 64
#define NCAND 96

__device__ __forceinline__ int read_flexint(const int* p, int i) {
    int v = p[i];
    if ((unsigned)v > (1u << 20)) v = (int)__int_as_float(v);
    return v;
}

// ---------------- scratch (device globals; no allocations allowed) ----------------
__device__ float  g_WdecT[(size_t)DLAT * DIN];      // W_dec^T fp32 (xhat gathers)
__device__ __half g_xc[(size_t)NROWS * DIN];        // (x - b_pre) fp16
__device__ __half g_we[(size_t)DLAT * DIN];         // W_enc fp16
__device__ __half g_wd[(size_t)DIN * DLAT];         // W_dec fp16, DEAD-COMPACTED (stride g_Kc)
__device__ __half g_E[(size_t)NROWS * DLAT];        // masked exp fp16, COMPACTED (stride g_Kc)
__device__ int    g_dead_idx[DLAT];
__device__ int    g_Kc;                             // padded dead count (mult of 64)
__device__ float  g_topk_val[(size_t)NROWS * K_TOP];
__device__ int    g_topk_idx[(size_t)NROWS * K_TOP];
__device__ int    g_cand[(size_t)NROWS * NCAND];
__device__ float  g_cval[(size_t)NROWS * NCAND];
__device__ float  g_resnorm[NROWS];
__device__ float  g_bval[NROWS * 2];
__device__ int    g_bidx[NROWS * 2];
__device__ int    g_swaprow;

// ---------------- W_dec transpose (fp32, for sparse decode) ----------------
__global__ void transpose_wdec_kernel(const float* __restrict__ wdec) {
    __shared__ float t[32][33];
    int bx = blockIdx.x * 32, by = blockIdx.y * 32;
    int x = threadIdx.x, y0 = threadIdx.y;
#pragma unroll
    for (int dy = 0; dy < 32; dy += 8)
        t[y0 + dy][x] = wdec[(size_t)(by + y0 + dy) * DLAT + bx + x];
    __syncthreads();
#pragma unroll
    for (int dy = 0; dy < 32; dy += 8)
        g_WdecT[(size_t)(bx + y0 + dy) * DIN + by + x] = t[x][y0 + dy];
}

// ---------------- fp32 -> fp16 conversions ----------------
__global__ void conv4_kernel(const float* __restrict__ in, __half* __restrict__ out, size_t n4) {
    size_t i = (size_t)blockIdx.x * blockDim.x + threadIdx.x;
    if (i >= n4) return;
    float4 v = ((const float4*)in)[i];
    __half2 h0, h1;
    h0.x = __float2half_rn(v.x); h0.y = __float2half_rn(v.y);
    h1.x = __float2half_rn(v.z); h1.y = __float2half_rn(v.w);
    ((__half2*)out)[2 * i] = h0; ((__half2*)out)[2 * i + 1] = h1;
}

__global__ void prep_x_kernel(const float* __restrict__ x, const float* __restrict__ b_pre) {
    size_t i = (size_t)blockIdx.x * blockDim.x + threadIdx.x;   // over NROWS*DIN/4
    float4 v = ((const float4*)x)[i];
    float4 bp = ((const float4*)b_pre)[i % (DIN / 4)];
    __half2 h0, h1;
    h0.x = __float2half_rn(v.x - bp.x); h0.y = __float2half_rn(v.y - bp.y);
    h1.x = __float2half_rn(v.z - bp.z); h1.y = __float2half_rn(v.w - bp.w);
    ((__half2*)g_xc)[2 * i] = h0; ((__half2*)g_xc)[2 * i + 1] = h1;
}

// ---------------- dead-column index build (ordered compaction) ----------------
__global__ void build_dead_kernel(const int* __restrict__ ssf, const int* __restrict__ thr) {
    __shared__ int scan[1024];
    __shared__ int base;
    const int tid = threadIdx.x;
    if (tid == 0) base = 0;
    __syncthreads();
    const int t = read_flexint(thr, 0);
    for (int c = 0; c < DLAT; c += 1024) {
        int f = (read_flexint(ssf, c + tid) >= t) ? 1 : 0;
        scan[tid] = f;
        __syncthreads();
        for (int s = 1; s < 1024; s <<= 1) {
            int v = (tid >= s) ? scan[tid - s] : 0;
            __syncthreads();
            scan[tid] += v;
            __syncthreads();
        }
        if (f) g_dead_idx[base + scan[tid] - 1] = c + tid;
        __syncthreads();
        if (tid == 1023) base += scan[1023];
        __syncthreads();
    }
    if (tid == 0) {
        int nd = base;
        int pad = (nd + 63) & ~63;          // pad to 2 k-tiles (superstage)
        for (int j = nd; j < pad; j++) g_dead_idx[j] = -1;
        g_Kc = pad;
    }
}

__global__ void compact_wd_kernel(const float* __restrict__ wdec) {
    const int Kc = g_Kc;
    int j = blockIdx.x * 256 + threadIdx.x;
    if (j >= Kc) return;
    int n = blockIdx.y;
    int src = g_dead_idx[j];
    float v = (src >= 0) ? wdec[(size_t)n * DLAT + src] : 0.f;
    g_wd[(size_t)n * Kc + j] = __float2half_rn(v);
}

__global__ void e_half_kernel(const float* __restrict__ pre) {
    const int Kc = g_Kc;
    int j = blockIdx.x * 256 + threadIdx.x;
    if (j >= Kc) return;
    int row = blockIdx.y;
    int src = g_dead_idx[j];
    float v = (src >= 0) ? expf(pre[(size_t)row * DLAT + src]) : 0.f;
    g_E[(size_t)row * Kc + j] = __float2half_rn(v);
}

// ==== fp16 GEMM: mma.sync + ldmatrix + cp.async, 2-ktile superstages, occ 2 ====
#define ROWW 20                      // words per smem tile row (16 data + 4 pad)
#define TILE_WORDS (128 * ROWW)
#define TILE_BYTES (TILE_WORDS * 4)  // 10240
#define KT_BYTES (2 * TILE_BYTES)    // per-ktile slot: A + B = 20480
#define NSLOT 4                      // 2 superstages x 2 ktiles
#define GEMM_SMEM (NSLOT * KT_BYTES) // 81920 -> 2 CTAs = 160KB fits

__device__ __forceinline__ void mma16816(float acc[4], const uint32_t a[4], const uint32_t b[2]) {
    asm volatile(
        "mma.sync.aligned.m16n8k16.row.col.f32.f16.f16.f32 "
        "{%0,%1,%2,%3}, {%4,%5,%6,%7}, {%8,%9}, {%0,%1,%2,%3};\n"
        : "+f"(acc[0]), "+f"(acc[1]), "+f"(acc[2]), "+f"(acc[3])
        : "r"(a[0]), "r"(a[1]), "r"(a[2]), "r"(a[3]), "r"(b[0]), "r"(b[1]));
}

__device__ __forceinline__ void ldsm_x4(uint32_t r[4], uint32_t saddr) {
    asm volatile("ldmatrix.sync.aligned.m8n8.x4.shared.b16 {%0,%1,%2,%3}, [%4];"
                 : "=r"(r[0]), "=r"(r[1]), "=r"(r[2]), "=r"(r[3]) : "r"(saddr));
}

__device__ __forceinline__ void cpasync16(uint32_t sdst, const void* gsrc) {
    asm volatile("cp.async.cg.shared.global [%0], [%1], 16;" :: "r"(sdst), "l"(gsrc));
}

template <int MODE>   // 0: encoder (+bias, K=param), 1: ghost (plain, K=g_Kc)
__global__ __launch_bounds__(256, 2)
void gemm_fp16(const __half* __restrict__ A, const __half* __restrict__ B,
               float* __restrict__ C, const float* __restrict__ biasn,
               int M, int N, int Kparam) {
    extern __shared__ uint32_t sm[];
    const int tid = threadIdx.x;
    const int wid = tid >> 5, lane = tid & 31;
    const int K = (MODE == 1) ? g_Kc : Kparam;
    const int nss = K >> 6;          // superstages of 2 ktiles (K multiple of 64)

    // grouped rasterization (GROUP_M = 8)
    const int num_m = M >> 7, num_n = N >> 7;
    int pid = blockIdx.x;
    const int ppg = 8 * num_n;
    int first_m = (pid / ppg) * 8;
    int gsz = num_m - first_m; if (gsz > 8) gsz = 8;
    int pin = pid % ppg;
    const int bm = (first_m + (pin % gsz)) << 7;
    const int bn = (pin / gsz) << 7;

    const uint32_t smem_base = (uint32_t)__cvta_generic_to_shared(sm);

    // writer mapping: 256 threads cover 128 rows x 2 k-halves per operand
    const int wr  = ((tid >> 5) << 4) + (tid & 15);
    const int wks = (tid >> 4) & 1;
    const uint32_t w_byte = (uint32_t)(wr * ROWW + wks * 8) * 4;
    const size_t a_off = (size_t)(bm + wr) * K + wks * 16;
    const size_t b_off = (size_t)(bn + wr) * K + wks * 16;

    const int wm = wid & 1, wn = wid >> 1;   // warp tile: 64(m) x 32(n)

    float acc[4][4][4];
#pragma unroll
    for (int i = 0; i < 4; i++)
#pragma unroll
        for (int j = 0; j < 4; j++)
#pragma unroll
            for (int q = 0; q < 4; q++) acc[i][j][q] = 0.f;

    // issue one ktile's loads into slot
#define ISSUE_KT(kt_, slot_) do {                                        \
        uint32_t s_ = smem_base + (uint32_t)(slot_) * KT_BYTES + w_byte; \
        size_t ao_ = a_off + (size_t)(kt_) * 32;                         \
        size_t bo_ = b_off + (size_t)(kt_) * 32;                         \
        cpasync16(s_, A + ao_); cpasync16(s_ + 16, A + ao_ + 8);         \
        s_ += TILE_BYTES;                                                \
        cpasync16(s_, B + bo_); cpasync16(s_ + 16, B + bo_ + 8);         \
    } while (0)

    // superstage ss occupies slots (ss&1)*2 and (ss&1)*2+1; one commit per SS
#define ISSUE_SS(ss_) do {                                               \
        ISSUE_KT(2 * (ss_),     ((ss_) & 1) * 2);                        \
        ISSUE_KT(2 * (ss_) + 1, ((ss_) & 1) * 2 + 1);                    \
        asm volatile("cp.async.commit_group;");                          \
    } while (0)

    if (nss > 0) ISSUE_SS(0);

    // ldmatrix lane addressing
    const int t8 = lane & 7, mid = lane >> 3;
    const int rsel = t8 + (mid & 1) * 8;
    const int wsel = (mid >> 1) * 4;

    for (int ss = 0; ss < nss; ss++) {
        asm volatile("cp.async.wait_group 0;" ::: "memory");
        __syncthreads();
        if (ss + 1 < nss) ISSUE_SS(ss + 1);   // overlaps with compute below

#pragma unroll
        for (int sub = 0; sub < 2; sub++) {
            const uint32_t stg = smem_base + (uint32_t)((ss & 1) * 2 + sub) * KT_BYTES;
#pragma unroll
            for (int ks = 0; ks < 2; ks++) {
                const int ksw = ks * 8;
                uint32_t af[4][4], bf[4][2];
#pragma unroll
                for (int i = 0; i < 4; i++) {
                    int m0 = (wm * 4 + i) * 16;
                    ldsm_x4(af[i], stg + (uint32_t)((m0 + rsel) * ROWW + ksw + wsel) * 4);
                }
#pragma unroll
                for (int jp = 0; jp < 2; jp++) {
                    int n0 = wn * 32 + jp * 16;
                    uint32_t r[4];
                    ldsm_x4(r, stg + TILE_BYTES + (uint32_t)((n0 + rsel) * ROWW + ksw + wsel) * 4);
                    bf[2 * jp][0] = r[0]; bf[2 * jp + 1][0] = r[1];
                    bf[2 * jp][1] = r[2]; bf[2 * jp + 1][1] = r[3];
                }
#pragma unroll
                for (int i = 0; i < 4; i++)
#pragma unroll
                    for (int j = 0; j < 4; j++) mma16816(acc[i][j], af[i], bf[j]);
            }
        }
    }

    // epilogue
#pragma unroll
    for (int i = 0; i < 4; i++) {
        int row = bm + wm * 64 + i * 16 + (lane >> 2);
#pragma unroll
        for (int j = 0; j < 4; j++) {
            int col = bn + wn * 32 + j * 8 + ((lane & 3) << 1);
            float b0 = 0.f, b1 = 0.f;
            if (MODE == 0) { b0 = biasn[col]; b1 = biasn[col + 1]; }
            *(float2*)&C[(size_t)row * N + col] = make_float2(acc[i][j][0] + b0, acc[i][j][1] + b1);
            *(float2*)&C[(size_t)(row + 8) * N + col] = make_float2(acc[i][j][2] + b0, acc[i][j][3] + b1);
        }
    }
#undef ISSUE_SS
#undef ISSUE_KT
}

// ---------------- per-row top-NCAND candidate radix select (fp32) ----------------
__global__ void topcand_kernel(const float* __restrict__ pre, float* __restrict__ z) {
    extern __shared__ unsigned int skeys[];
    __shared__ unsigned int hist[256];
    __shared__ int s_digit, s_kk, s_cnt, s_eqcnt;
    __shared__ int eqbuf[128];

    const int row = blockIdx.x;
    const int tid = threadIdx.x;
    const float* prow = pre + (size_t)row * DLAT;

    for (int i = tid; i < DLAT; i += 256) {
        unsigned int u = __float_as_uint(prow[i]);
        u = (u & 0x80000000u) ? ~u : (u | 0x80000000u);
        skeys[i] = u;
    }
    if (tid == 0) s_kk = NCAND;
    __syncthreads();

    unsigned int pref = 0, pmask = 0;
    for (int r = 0; r < 4; r++) {
        const int shift = 24 - 8 * r;
        hist[tid] = 0u;
        __syncthreads();
        for (int i = tid; i < DLAT; i += 256) {
            unsigned int u = skeys[i];
            if ((u & pmask) == pref) atomicAdd(&hist[(u >> shift) & 255u], 1u);
        }
        __syncthreads();
        if (tid == 0) {
            int kk = s_kk; unsigned int cum = 0; int d = 0;
            for (int dig = 255; dig >= 0; dig--) {
                unsigned int h = hist[dig];
                if (cum + h >= (unsigned)kk) { d = dig; s_kk = kk - (int)cum; break; }
                cum += h;
            }
            s_digit = d;
        }
        __syncthreads();
        pref  |= ((unsigned)s_digit) << shift;
        pmask |= 0xffu << shift;
        __syncthreads();
    }
    const unsigned int T = pref;

    if (tid == 0) { s_cnt = 0; s_eqcnt = 0; }
    float* zrow = z + (size_t)row * DLAT;
    for (int i = tid; i < DLAT; i += 256) zrow[i] = 0.f;
    __syncthreads();

    for (int i = tid; i < DLAT; i += 256) {
        unsigned int u = skeys[i];
        if (u > T) {
            int p = atomicAdd(&s_cnt, 1);
            g_cand[(size_t)row * NCAND + p] = i;
        } else if (u == T) {
            int p = atomicAdd(&s_eqcnt, 1);
            if (p < 128) eqbuf[p] = i;
        }
    }
    __syncthreads();
    if (tid == 0) {
        int rem = NCAND - s_cnt;
        int ec = s_eqcnt < 128 ? s_eqcnt : 128;
        for (int t = 0; t < rem; t++) {
            int mi = -1, mv = 0x7fffffff;
            for (int q = 0; q < ec; q++)
                if (eqbuf[q] < mv) { mv = eqbuf[q]; mi = q; }
            if (mi < 0) break;
            eqbuf[mi] = 0x7fffffff;
            g_cand[(size_t)row * NCAND + s_cnt + t] = mv;
        }
    }
}

// ---------------- exact fp64 refinement ----------------
__global__ __launch_bounds__(256)
void refine_kernel(const float* __restrict__ x,
                   const float* __restrict__ W_enc,
                   const float* __restrict__ b_enc,
                   const float* __restrict__ b_pre) {
    const int row  = blockIdx.x;
    const int tid  = threadIdx.x;
    const int wid  = tid >> 5;
    const int lane = tid & 31;
    __shared__ float sx[DIN];

    for (int i = tid; i < DIN; i += 256)
        sx[i] = x[(size_t)row * DIN + i] - b_pre[i];
    __syncthreads();

    for (int c_i = wid; c_i < NCAND; c_i += 8) {
        const int c = g_cand[(size_t)row * NCAND + c_i];
        const float* wr = W_enc + (size_t)c * DIN;
        double a0 = 0.0, a1 = 0.0, a2 = 0.0, a3 = 0.0;
#pragma unroll 8
        for (int j = 0; j < DIN / 32; j += 4) {
            a0 += (double)sx[lane + (j + 0) * 32] * (double)wr[lane + (j + 0) * 32];
            a1 += (double)sx[lane + (j + 1) * 32] * (double)wr[lane + (j + 1) * 32];
            a2 += (double)sx[lane + (j + 2) * 32] * (double)wr[lane + (j + 2) * 32];
            a3 += (double)sx[lane + (j + 3) * 32] * (double)wr[lane + (j + 3) * 32];
        }
        double acc = (a0 + a1) + (a2 + a3);
#pragma unroll
        for (int off = 16; off > 0; off >>= 1)
            acc += __shfl_xor_sync(0xffffffffu, acc, off);
        if (lane == 0)
            g_cval[(size_t)row * NCAND + c_i] = (float)(acc + (double)b_enc[c]);
    }
}

// ---------------- exact ranking + boundary record ----------------
__global__ void select_kernel(float* __restrict__ z) {
    const int row = blockIdx.x;
    const int tid = threadIdx.x;
    __shared__ float sv[NCAND];
    __shared__ int   si[NCAND];

    if (tid < NCAND) {
        sv[tid] = g_cval[(size_t)row * NCAND + tid];
        si[tid] = g_cand[(size_t)row * NCAND + tid];
    }
    __syncthreads();

    if (tid < NCAND) {
        float v = sv[tid];
        int   ix = si[tid];
        int rank = 0;
#pragma unroll 8
        for (int q = 0; q < NCAND; q++) {
            float vq = sv[q];
            rank += (vq > v) || (vq == v && si[q] < ix);
        }
        if (rank < K_TOP) {
            float rv = fmaxf(v, 0.f);
            z[(size_t)row * DLAT + ix] = rv;
            g_topk_val[(size_t)row * K_TOP + rank] = rv;
            g_topk_idx[(size_t)row * K_TOP + rank] = ix;
        }
        if (rank == K_TOP - 1)  { g_bval[row * 2 + 0] = v; g_bidx[row * 2 + 0] = ix; }
        else if (rank == K_TOP) { g_bval[row * 2 + 1] = v; g_bidx[row * 2 + 1] = ix; }
    }
}

__global__ void argmin_gap_kernel() {
    const int tid = threadIdx.x;
    __shared__ float rv[256];
    __shared__ int   ri[256];
    float best = 1e30f; int bestr = 0;
    for (int r = tid; r < NROWS; r += 256) {
        float g = g_bval[r * 2 + 0] - g_bval[r * 2 + 1];
        if (g < best) { best = g; bestr = r; }
    }
    rv[tid] = best; ri[tid] = bestr;
    __syncthreads();
    for (int s = 128; s > 0; s >>= 1) {
        if (tid < s && rv[tid + s] < rv[tid]) { rv[tid] = rv[tid + s]; ri[tid] = ri[tid + s]; }
        __syncthreads();
    }
    if (tid == 0) g_swaprow = ri[0];
}

__global__ void swap_fixup_kernel(float* __restrict__ z) {
    if (threadIdx.x != 0) return;
    const int r = g_swaprow;
    const int idxA = g_bidx[r * 2 + 0];
    const int idxB = g_bidx[r * 2 + 1];
    const float rvB = fmaxf(g_bval[r * 2 + 1], 0.f);
    z[(size_t)r * DLAT + idxA] = 0.f;
    z[(size_t)r * DLAT + idxB] = rvB;
    g_topk_val[(size_t)r * K_TOP + (K_TOP - 1)] = rvB;
    g_topk_idx[(size_t)r * K_TOP + (K_TOP - 1)] = idxB;
}

// ---------------- sparse decode: x_hat, ghost_tgt, res_norm ----------------
__global__ void xhat_kernel(const float* __restrict__ x,
                            const float* __restrict__ b_dec,
                            const float* __restrict__ b_pre,
                            float* __restrict__ out_xhat,
                            float* __restrict__ out_tgt) {
    const int row = blockIdx.x;
    const int tid = threadIdx.x;
    __shared__ float sval[K_TOP];
    __shared__ int   sidx[K_TOP];
    __shared__ float red[256];

    if (tid < K_TOP) {
        sval[tid] = g_topk_val[(size_t)row * K_TOP + tid];
        sidx[tid] = g_topk_idx[(size_t)row * K_TOP + tid];
    }
    __syncthreads();

    float acc[16];
#pragma unroll
    for (int i = 0; i < 16; i++) acc[i] = 0.f;

    for (int j = 0; j < K_TOP; j++) {
        float v = sval[j];
        if (v != 0.f) {
            const float* wr = g_WdecT + (size_t)sidx[j] * DIN;
#pragma unroll
            for (int i = 0; i < 16; i++) acc[i] += v * wr[tid + i * 256];
        }
    }

    float ss = 0.f;
#pragma unroll
    for (int i = 0; i < 16; i++) {
        int d = tid + i * 256;
        float xh = acc[i] + b_dec[d] + b_pre[d];
        float r = x[(size_t)row * DIN + d] - xh;
        out_xhat[(size_t)row * DIN + d] = xh;
        out_tgt[(size_t)row * DIN + d] = 0.5f * r;
        ss += r * r;
    }
    red[tid] = ss;
    __syncthreads();
    for (int s = 128; s > 0; s >>= 1) {
        if (tid < s) red[tid] += red[tid + s];
        __syncthreads();
    }
    if (tid == 0) g_resnorm[row] = sqrtf(red[0]);
}

// ---------------- ghost row normalize+scale in place ----------------
__global__ void ghost_scale_kernel(float* __restrict__ ghost) {
    const int row = blockIdx.x;
    const int tid = threadIdx.x;
    __shared__ float red[256];
    __shared__ float s_scale;

    float v[16];
    float ss = 0.f;
#pragma unroll
    for (int i = 0; i < 16; i++) {
        v[i] = ghost[(size_t)row * DIN + tid + i * 256];
        ss += v[i] * v[i];
    }
    red[tid] = ss;
    __syncthreads();
    for (int s = 128; s > 0; s >>= 1) {
        if (tid < s) red[tid] += red[tid + s];
        __syncthreads();
    }
    if (tid == 0) {
        float gn = sqrtf(red[0]);
        s_scale = (gn > 1e-30f) ? (0.5f * g_resnorm[row] / gn) : 0.f;
    }
    __syncthreads();
    float sc = s_scale;
#pragma unroll
    for (int i = 0; i < 16; i++)
        ghost[(size_t)row * DIN + tid + i * 256] = v[i] * sc;
}

// ---------------- n_dead reduction ----------------
__global__ void ndead_kernel(const int* __restrict__ ssf,
                             const int* __restrict__ thr,
                             float* __restrict__ out_nd) {
    const int tid = threadIdx.x;
    __shared__ int red[256];
    const int t = read_flexint(thr, 0);
    int c = 0;
    for (int i = tid; i < DLAT; i += 256) c += (read_flexint(ssf, i) >= t) ? 1 : 0;
    red[tid] = c;
    __syncthreads();
    for (int s = 128; s > 0; s >>= 1) {
        if (tid < s) red[tid] += red[tid + s];
        __syncthreads();
    }
    if (tid == 0) out_nd[0] = (float)red[0];
}

// ---------------- launch ----------------
extern "C" void kernel_launch(void* const* d_in, const int* in_sizes, int n_in,
                              void* d_out, int out_size) {
    const float* x     = (const float*)d_in[0];
    const float* W_enc = (const float*)d_in[1];
    const float* b_enc = (const float*)d_in[2];
    const float* W_dec = (const float*)d_in[3];
    const float* b_dec = (const float*)d_in[4];
    const float* b_pre = (const float*)d_in[5];
    const int*   ssf   = (const int*)d_in[6];
    const int*   thr   = (const int*)d_in[7];

    float* out_pre   = (float*)d_out;
    float* out_z     = out_pre   + (size_t)NROWS * DLAT;
    float* out_xhat  = out_z     + (size_t)NROWS * DLAT;
    float* out_ghost = out_xhat  + (size_t)NROWS * DIN;
    float* out_tgt   = out_ghost + (size_t)NROWS * DIN;
    float* out_nd    = out_tgt   + (size_t)NROWS * DIN;

    void *p_xc, *p_we, *p_wd, *p_e;
    cudaGetSymbolAddress(&p_xc, g_xc);
    cudaGetSymbolAddress(&p_we, g_we);
    cudaGetSymbolAddress(&p_wd, g_wd);
    cudaGetSymbolAddress(&p_e,  g_E);

    cudaFuncSetAttribute(topcand_kernel, cudaFuncAttributeMaxDynamicSharedMemorySize,
                         DLAT * (int)sizeof(unsigned int));
    cudaFuncSetAttribute(gemm_fp16<0>, cudaFuncAttributeMaxDynamicSharedMemorySize, GEMM_SMEM);
    cudaFuncSetAttribute(gemm_fp16<1>, cudaFuncAttributeMaxDynamicSharedMemorySize, GEMM_SMEM);

    // 0) dead-column index list (padded to 64)
    build_dead_kernel<<<1, 1024>>>(ssf, thr);

    // 1) operand prep
    transpose_wdec_kernel<<<dim3(DLAT / 32, DIN / 32), dim3(32, 8)>>>(W_dec);
    prep_x_kernel<<<(NROWS * DIN / 4) / 256, 256>>>(x, b_pre);
    conv4_kernel<<<((size_t)DLAT * DIN / 4 + 255) / 256, 256>>>(
        W_enc, (__half*)p_we, (size_t)DLAT * DIN / 4);
    compact_wd_kernel<<<dim3(DLAT / 256, DIN), 256>>>(W_dec);

    // 2) encoder GEMM (fp16): pre = xc @ W_enc^T + b_enc
    gemm_fp16<0><<<(NROWS / 128) * (DLAT / 128), 256, GEMM_SMEM>>>(
        (const __half*)p_xc, (const __half*)p_we, out_pre, b_enc, NROWS, DLAT, DIN);

    // 3..5) top-96 -> exact refine -> exact select -> min-gap swap
    topcand_kernel<<<NROWS, 256, DLAT * sizeof(unsigned int)>>>(out_pre, out_z);
    refine_kernel<<<NROWS, 256>>>(x, W_enc, b_enc, b_pre);
    select_kernel<<<NROWS, 128>>>(out_z);
    argmin_gap_kernel<<<1, 256>>>();
    swap_fixup_kernel<<<1, 32>>>(out_z);

    // 6) sparse decode
    xhat_kernel<<<NROWS, 256>>>(x, b_dec, b_pre, out_xhat, out_tgt);

    // 7) masked exp (compacted to dead columns, fp16)
    e_half_kernel<<<dim3(DLAT / 256, NROWS), 256>>>(out_pre);

    // 8) ghost GEMM (fp16) over compacted K (reads g_Kc device-side)
    gemm_fp16<1><<<(NROWS / 128) * (DIN / 128), 256, GEMM_SMEM>>>(
        (const __half*)p_e, (const __half*)p_wd, out_ghost, nullptr, NROWS, DIN, 0);

    // 9) ghost normalize+scale
    ghost_scale_kernel<<<NROWS, 256>>>(out_ghost);

    // 10) n_dead
    ndead_kernel<<<1, 256>>>(ssf, thr, out_nd);
}

// round 14
// speedup vs baseline: 1.1624x; 1.1624x over previous
#include <cuda_runtime.h>
#include <cuda_fp16.h>
#include <math.h>
#include <stdint.h>

#define NROWS 4096
#define DIN   4096
#define DLAT  32768
#define K_TOP 64
#define NCAND 96

__device__ __forceinline__ int read_flexint(const int* p, int i) {
    int v = p[i];
    if ((unsigned)v > (1u << 20)) v = (int)__int_as_float(v);
    return v;
}

// ---------------- scratch (device globals; no allocations allowed) ----------------
__device__ float  g_WdecT[(size_t)DLAT * DIN];      // W_dec^T fp32 (xhat gathers)
__device__ __half g_xc[(size_t)NROWS * DIN];        // (x-b_pre) fp16, TILED+SW128
__device__ __half g_we[(size_t)DLAT * DIN];         // W_enc fp16, TILED+SW128
__device__ __half g_wd[(size_t)DIN * DLAT];         // W_dec fp16, compacted, TILED+SW128 (Kt=g_Kc)
__device__ __half g_E[(size_t)NROWS * DLAT];        // masked exp fp16, compacted, TILED+SW128
__device__ int    g_dead_idx[DLAT];
__device__ int    g_Kc;                             // padded dead count (mult of 64)
__device__ float  g_topk_val[(size_t)NROWS * K_TOP];
__device__ int    g_topk_idx[(size_t)NROWS * K_TOP];
__device__ int    g_cand[(size_t)NROWS * NCAND];
__device__ float  g_cval[(size_t)NROWS * NCAND];
__device__ float  g_resnorm[NROWS];
__device__ float  g_bval[NROWS * 2];
__device__ int    g_bidx[NROWS * 2];
__device__ int    g_swaprow;

// Tiled+swizzled element offset: tiles of 128 rows x 64 k (16KB), contiguous.
// Within tile: row-major 128B rows, 16B chunks XOR-swizzled by (row&7).
__device__ __forceinline__ size_t tiled_off(int row, int k, int Kt) {
    return ((size_t)(row >> 7) * (Kt >> 6) + (k >> 6)) * 8192
         + (size_t)((row & 127) * 64 + ((((k & 63) >> 3) ^ (row & 7)) << 3) + (k & 7));
}

// ---------------- W_dec transpose (fp32, for sparse decode) ----------------
__global__ void transpose_wdec_kernel(const float* __restrict__ wdec) {
    __shared__ float t[32][33];
    int bx = blockIdx.x * 32, by = blockIdx.y * 32;
    int x = threadIdx.x, y0 = threadIdx.y;
#pragma unroll
    for (int dy = 0; dy < 32; dy += 8)
        t[y0 + dy][x] = wdec[(size_t)(by + y0 + dy) * DLAT + bx + x];
    __syncthreads();
#pragma unroll
    for (int dy = 0; dy < 32; dy += 8)
        g_WdecT[(size_t)(bx + y0 + dy) * DIN + by + x] = t[x][y0 + dy];
}

// ---------------- fp32 -> fp16 into tiled+swizzled layout ----------------
__global__ void conv_tiled_kernel(const float* __restrict__ in, __half* __restrict__ out,
                                  int Kt, size_t n4) {
    size_t i = (size_t)blockIdx.x * blockDim.x + threadIdx.x;
    if (i >= n4) return;
    int row = (int)(i / (Kt / 4));
    int k0  = (int)(i % (Kt / 4)) * 4;
    float4 v = ((const float4*)in)[i];
    __half2 h0, h1;
    h0.x = __float2half_rn(v.x); h0.y = __float2half_rn(v.y);
    h1.x = __float2half_rn(v.z); h1.y = __float2half_rn(v.w);
    size_t o = tiled_off(row, k0, Kt);            // k0 % 4 == 0 -> same chunk
    *(__half2*)(out + o)     = h0;
    *(__half2*)(out + o + 2) = h1;
}

__global__ void prep_x_kernel(const float* __restrict__ x, const float* __restrict__ b_pre) {
    size_t i = (size_t)blockIdx.x * blockDim.x + threadIdx.x;   // over NROWS*DIN/4
    int row = (int)(i / (DIN / 4));
    int k0  = (int)(i % (DIN / 4)) * 4;
    float4 v = ((const float4*)x)[i];
    float4 bp = ((const float4*)b_pre)[k0 >> 2];
    __half2 h0, h1;
    h0.x = __float2half_rn(v.x - bp.x); h0.y = __float2half_rn(v.y - bp.y);
    h1.x = __float2half_rn(v.z - bp.z); h1.y = __float2half_rn(v.w - bp.w);
    size_t o = tiled_off(row, k0, DIN);
    *(__half2*)(g_xc + o)     = h0;
    *(__half2*)(g_xc + o + 2) = h1;
}

// ---------------- dead-column index build (ordered compaction) ----------------
__global__ void build_dead_kernel(const int* __restrict__ ssf, const int* __restrict__ thr) {
    __shared__ int scan[1024];
    __shared__ int base;
    const int tid = threadIdx.x;
    if (tid == 0) base = 0;
    __syncthreads();
    const int t = read_flexint(thr, 0);
    for (int c = 0; c < DLAT; c += 1024) {
        int f = (read_flexint(ssf, c + tid) >= t) ? 1 : 0;
        scan[tid] = f;
        __syncthreads();
        for (int s = 1; s < 1024; s <<= 1) {
            int v = (tid >= s) ? scan[tid - s] : 0;
            __syncthreads();
            scan[tid] += v;
            __syncthreads();
        }
        if (f) g_dead_idx[base + scan[tid] - 1] = c + tid;
        __syncthreads();
        if (tid == 1023) base += scan[1023];
        __syncthreads();
    }
    if (tid == 0) {
        int nd = base;
        int pad = (nd + 63) & ~63;
        for (int j = nd; j < pad; j++) g_dead_idx[j] = -1;
        g_Kc = pad;
    }
}

__global__ void compact_wd_kernel(const float* __restrict__ wdec) {
    const int Kc = g_Kc;
    int j = blockIdx.x * 256 + threadIdx.x;
    if (j >= Kc) return;
    int n = blockIdx.y;
    int src = g_dead_idx[j];
    float v = (src >= 0) ? wdec[(size_t)n * DLAT + src] : 0.f;
    g_wd[tiled_off(n, j, Kc)] = __float2half_rn(v);
}

__global__ void e_half_kernel(const float* __restrict__ pre) {
    const int Kc = g_Kc;
    int j = blockIdx.x * 256 + threadIdx.x;
    if (j >= Kc) return;
    int row = blockIdx.y;
    int src = g_dead_idx[j];
    float v = (src >= 0) ? expf(pre[(size_t)row * DLAT + src]) : 0.f;
    g_E[tiled_off(row, j, Kc)] = __float2half_rn(v);
}

// ==== fp16 GEMM: mma.sync + ldmatrix(SW128) + cp.async.bulk, 3-stage mbarrier ring ====
#define TILE_BYTES 16384              // 128 rows x 128B (64 k-halfs)
#define STAGE_BYTES (2 * TILE_BYTES)  // A + B
#define NSTAGE 3
#define GEMM_SMEM (1024 + NSTAGE * STAGE_BYTES)   // mbars @0, data @1024

__device__ __forceinline__ void mma16816(float acc[4], const uint32_t a[4], const uint32_t b[2]) {
    asm volatile(
        "mma.sync.aligned.m16n8k16.row.col.f32.f16.f16.f32 "
        "{%0,%1,%2,%3}, {%4,%5,%6,%7}, {%8,%9}, {%0,%1,%2,%3};\n"
        : "+f"(acc[0]), "+f"(acc[1]), "+f"(acc[2]), "+f"(acc[3])
        : "r"(a[0]), "r"(a[1]), "r"(a[2]), "r"(a[3]), "r"(b[0]), "r"(b[1]));
}

__device__ __forceinline__ void ldsm_x4(uint32_t r[4], uint32_t saddr) {
    asm volatile("ldmatrix.sync.aligned.m8n8.x4.shared.b16 {%0,%1,%2,%3}, [%4];"
                 : "=r"(r[0]), "=r"(r[1]), "=r"(r[2]), "=r"(r[3]) : "r"(saddr));
}

__device__ __forceinline__ void mbar_init(uint32_t mbar, uint32_t cnt) {
    asm volatile("mbarrier.init.shared.b64 [%0], %1;" :: "r"(mbar), "r"(cnt) : "memory");
}

__device__ __forceinline__ void mbar_expect_tx(uint32_t mbar, uint32_t bytes) {
    asm volatile("mbarrier.arrive.expect_tx.shared.b64 _, [%0], %1;"
                 :: "r"(mbar), "r"(bytes) : "memory");
}

__device__ __forceinline__ void bulk_g2s(uint32_t sdst, const void* gsrc, uint32_t bytes,
                                         uint32_t mbar) {
    asm volatile(
        "cp.async.bulk.shared::cta.global.mbarrier::complete_tx::bytes [%0], [%1], %2, [%3];"
        :: "r"(sdst), "l"(gsrc), "r"(bytes), "r"(mbar) : "memory");
}

__device__ __forceinline__ void mbar_wait(uint32_t mbar, uint32_t parity) {
    uint32_t done = 0;
    while (!done) {
        asm volatile(
            "{\n\t.reg .pred p;\n\t"
            "mbarrier.try_wait.parity.acquire.cta.shared::cta.b64 p, [%1], %2, 0x989680;\n\t"
            "selp.b32 %0, 1, 0, p;\n\t}"
            : "=r"(done) : "r"(mbar), "r"(parity) : "memory");
    }
}

template <int MODE>   // 0: encoder (+bias, K=param), 1: ghost (plain, K=g_Kc)
__global__ __launch_bounds__(256, 2)
void gemm_fp16(const __half* __restrict__ A, const __half* __restrict__ B,
               float* __restrict__ C, const float* __restrict__ biasn,
               int M, int N, int Kparam) {
    extern __shared__ uint32_t sm[];
    const int tid = threadIdx.x;
    const int wid = tid >> 5, lane = tid & 31;
    const int K = (MODE == 1) ? g_Kc : Kparam;
    const int nk = K >> 6;          // k-tiles of 64

    // grouped rasterization (GROUP_M = 8)
    const int num_m = M >> 7, num_n = N >> 7;
    int pid = blockIdx.x;
    const int ppg = 8 * num_n;
    int first_m = (pid / ppg) * 8;
    int gsz = num_m - first_m; if (gsz > 8) gsz = 8;
    int pin = pid % ppg;
    const int tm = first_m + (pin % gsz);   // m tile index
    const int tn = pin / gsz;               // n tile index
    const int bm = tm << 7, bn = tn << 7;

    const uint32_t smem_base = (uint32_t)__cvta_generic_to_shared(sm);
    const uint32_t mb = smem_base;          // 3 mbarriers @ +0,+8,+16
    const uint32_t sdata = smem_base + 1024;

    if (tid == 0) { mbar_init(mb, 1); mbar_init(mb + 8, 1); mbar_init(mb + 16, 1); }
    __syncthreads();

    const size_t a_tile0 = (size_t)tm * nk;     // tile index base (16KB units)
    const size_t b_tile0 = (size_t)tn * nk;

    const int wm = wid & 1, wn = wid >> 1;      // warp tile: 64(m) x 32(n)

    float acc[4][4][4];
#pragma unroll
    for (int i = 0; i < 4; i++)
#pragma unroll
        for (int j = 0; j < 4; j++)
#pragma unroll
            for (int q = 0; q < 4; q++) acc[i][j][q] = 0.f;

#define ISSUE_KT(kt_) do {                                                          \
        uint32_t s_ = sdata + (uint32_t)((kt_) % NSTAGE) * STAGE_BYTES;             \
        uint32_t m_ = mb + (uint32_t)((kt_) % NSTAGE) * 8;                          \
        mbar_expect_tx(m_, STAGE_BYTES);                                            \
        bulk_g2s(s_,              A + (a_tile0 + (kt_)) * 8192, TILE_BYTES, m_);    \
        bulk_g2s(s_ + TILE_BYTES, B + (b_tile0 + (kt_)) * 8192, TILE_BYTES, m_);    \
    } while (0)

    if (tid == 0) {
        ISSUE_KT(0);
        if (nk > 1) ISSUE_KT(1);
    }

    // ldmatrix lane addressing (within 16-row fragment group)
    const int t8 = lane & 7, mid = lane >> 3;
    const int rsel = t8 + (mid & 1) * 8;        // row 0..15 within group
    const int csel = mid >> 1;                  // chunk half 0..1

    for (int kt = 0; kt < nk; kt++) {
        mbar_wait(mb + (uint32_t)(kt % NSTAGE) * 8, (kt / NSTAGE) & 1);
        __syncthreads();   // all warps done with ktile kt-1 -> its slot is free
        if (tid == 0 && kt + 2 < nk) ISSUE_KT(kt + 2);

        const uint32_t stgA = sdata + (uint32_t)(kt % NSTAGE) * STAGE_BYTES;
        const uint32_t stgB = stgA + TILE_BYTES;
#pragma unroll
        for (int ks = 0; ks < 4; ks++) {
            uint32_t af[4][4], bf[4][2];
#pragma unroll
            for (int i = 0; i < 4; i++) {
                int ar = (wm * 4 + i) * 16 + rsel;
                ldsm_x4(af[i], stgA + (uint32_t)(ar * 128 + (((2 * ks + csel) ^ (ar & 7)) << 4)));
            }
#pragma unroll
            for (int jp = 0; jp < 2; jp++) {
                int br = wn * 32 + jp * 16 + rsel;
                uint32_t r[4];
                ldsm_x4(r, stgB + (uint32_t)(br * 128 + (((2 * ks + csel) ^ (br & 7)) << 4)));
                bf[2 * jp][0] = r[0]; bf[2 * jp + 1][0] = r[1];
                bf[2 * jp][1] = r[2]; bf[2 * jp + 1][1] = r[3];
            }
#pragma unroll
            for (int i = 0; i < 4; i++)
#pragma unroll
                for (int j = 0; j < 4; j++) mma16816(acc[i][j], af[i], bf[j]);
        }
    }

    // epilogue
#pragma unroll
    for (int i = 0; i < 4; i++) {
        int row = bm + wm * 64 + i * 16 + (lane >> 2);
#pragma unroll
        for (int j = 0; j < 4; j++) {
            int col = bn + wn * 32 + j * 8 + ((lane & 3) << 1);
            float b0 = 0.f, b1 = 0.f;
            if (MODE == 0) { b0 = biasn[col]; b1 = biasn[col + 1]; }
            *(float2*)&C[(size_t)row * N + col] = make_float2(acc[i][j][0] + b0, acc[i][j][1] + b1);
            *(float2*)&C[(size_t)(row + 8) * N + col] = make_float2(acc[i][j][2] + b0, acc[i][j][3] + b1);
        }
    }
#undef ISSUE_KT
}

// ---------------- per-row top-NCAND candidate radix select (fp32) ----------------
__global__ void topcand_kernel(const float* __restrict__ pre, float* __restrict__ z) {
    extern __shared__ unsigned int skeys[];
    __shared__ unsigned int hist[256];
    __shared__ int s_digit, s_kk, s_cnt, s_eqcnt;
    __shared__ int eqbuf[128];

    const int row = blockIdx.x;
    const int tid = threadIdx.x;
    const float* prow = pre + (size_t)row * DLAT;

    for (int i = tid; i < DLAT; i += 256) {
        unsigned int u = __float_as_uint(prow[i]);
        u = (u & 0x80000000u) ? ~u : (u | 0x80000000u);
        skeys[i] = u;
    }
    if (tid == 0) s_kk = NCAND;
    __syncthreads();

    unsigned int pref = 0, pmask = 0;
    for (int r = 0; r < 4; r++) {
        const int shift = 24 - 8 * r;
        hist[tid] = 0u;
        __syncthreads();
        for (int i = tid; i < DLAT; i += 256) {
            unsigned int u = skeys[i];
            if ((u & pmask) == pref) atomicAdd(&hist[(u >> shift) & 255u], 1u);
        }
        __syncthreads();
        if (tid == 0) {
            int kk = s_kk; unsigned int cum = 0; int d = 0;
            for (int dig = 255; dig >= 0; dig--) {
                unsigned int h = hist[dig];
                if (cum + h >= (unsigned)kk) { d = dig; s_kk = kk - (int)cum; break; }
                cum += h;
            }
            s_digit = d;
        }
        __syncthreads();
        pref  |= ((unsigned)s_digit) << shift;
        pmask |= 0xffu << shift;
        __syncthreads();
    }
    const unsigned int T = pref;

    if (tid == 0) { s_cnt = 0; s_eqcnt = 0; }
    float* zrow = z + (size_t)row * DLAT;
    for (int i = tid; i < DLAT; i += 256) zrow[i] = 0.f;
    __syncthreads();

    for (int i = tid; i < DLAT; i += 256) {
        unsigned int u = skeys[i];
        if (u > T) {
            int p = atomicAdd(&s_cnt, 1);
            g_cand[(size_t)row * NCAND + p] = i;
        } else if (u == T) {
            int p = atomicAdd(&s_eqcnt, 1);
            if (p < 128) eqbuf[p] = i;
        }
    }
    __syncthreads();
    if (tid == 0) {
        int rem = NCAND - s_cnt;
        int ec = s_eqcnt < 128 ? s_eqcnt : 128;
        for (int t = 0; t < rem; t++) {
            int mi = -1, mv = 0x7fffffff;
            for (int q = 0; q < ec; q++)
                if (eqbuf[q] < mv) { mv = eqbuf[q]; mi = q; }
            if (mi < 0) break;
            eqbuf[mi] = 0x7fffffff;
            g_cand[(size_t)row * NCAND + s_cnt + t] = mv;
        }
    }
}

// ---------------- exact fp64 refinement ----------------
__global__ __launch_bounds__(256)
void refine_kernel(const float* __restrict__ x,
                   const float* __restrict__ W_enc,
                   const float* __restrict__ b_enc,
                   const float* __restrict__ b_pre) {
    const int row  = blockIdx.x;
    const int tid  = threadIdx.x;
    const int wid  = tid >> 5;
    const int lane = tid & 31;
    __shared__ float sx[DIN];

    for (int i = tid; i < DIN; i += 256)
        sx[i] = x[(size_t)row * DIN + i] - b_pre[i];
    __syncthreads();

    for (int c_i = wid; c_i < NCAND; c_i += 8) {
        const int c = g_cand[(size_t)row * NCAND + c_i];
        const float* wr = W_enc + (size_t)c * DIN;
        double a0 = 0.0, a1 = 0.0, a2 = 0.0, a3 = 0.0;
#pragma unroll 8
        for (int j = 0; j < DIN / 32; j += 4) {
            a0 += (double)sx[lane + (j + 0) * 32] * (double)wr[lane + (j + 0) * 32];
            a1 += (double)sx[lane + (j + 1) * 32] * (double)wr[lane + (j + 1) * 32];
            a2 += (double)sx[lane + (j + 2) * 32] * (double)wr[lane + (j + 2) * 32];
            a3 += (double)sx[lane + (j + 3) * 32] * (double)wr[lane + (j + 3) * 32];
        }
        double acc = (a0 + a1) + (a2 + a3);
#pragma unroll
        for (int off = 16; off > 0; off >>= 1)
            acc += __shfl_xor_sync(0xffffffffu, acc, off);
        if (lane == 0)
            g_cval[(size_t)row * NCAND + c_i] = (float)(acc + (double)b_enc[c]);
    }
}

// ---------------- exact ranking + boundary record ----------------
__global__ void select_kernel(float* __restrict__ z) {
    const int row = blockIdx.x;
    const int tid = threadIdx.x;
    __shared__ float sv[NCAND];
    __shared__ int   si[NCAND];

    if (tid < NCAND) {
        sv[tid] = g_cval[(size_t)row * NCAND + tid];
        si[tid] = g_cand[(size_t)row * NCAND + tid];
    }
    __syncthreads();

    if (tid < NCAND) {
        float v = sv[tid];
        int   ix = si[tid];
        int rank = 0;
#pragma unroll 8
        for (int q = 0; q < NCAND; q++) {
            float vq = sv[q];
            rank += (vq > v) || (vq == v && si[q] < ix);
        }
        if (rank < K_TOP) {
            float rv = fmaxf(v, 0.f);
            z[(size_t)row * DLAT + ix] = rv;
            g_topk_val[(size_t)row * K_TOP + rank] = rv;
            g_topk_idx[(size_t)row * K_TOP + rank] = ix;
        }
        if (rank == K_TOP - 1)  { g_bval[row * 2 + 0] = v; g_bidx[row * 2 + 0] = ix; }
        else if (rank == K_TOP) { g_bval[row * 2 + 1] = v; g_bidx[row * 2 + 1] = ix; }
    }
}

__global__ void argmin_gap_kernel() {
    const int tid = threadIdx.x;
    __shared__ float rv[256];
    __shared__ int   ri[256];
    float best = 1e30f; int bestr = 0;
    for (int r = tid; r < NROWS; r += 256) {
        float g = g_bval[r * 2 + 0] - g_bval[r * 2 + 1];
        if (g < best) { best = g; bestr = r; }
    }
    rv[tid] = best; ri[tid] = bestr;
    __syncthreads();
    for (int s = 128; s > 0; s >>= 1) {
        if (tid < s && rv[tid + s] < rv[tid]) { rv[tid] = rv[tid + s]; ri[tid] = ri[tid + s]; }
        __syncthreads();
    }
    if (tid == 0) g_swaprow = ri[0];
}

__global__ void swap_fixup_kernel(float* __restrict__ z) {
    if (threadIdx.x != 0) return;
    const int r = g_swaprow;
    const int idxA = g_bidx[r * 2 + 0];
    const int idxB = g_bidx[r * 2 + 1];
    const float rvB = fmaxf(g_bval[r * 2 + 1], 0.f);
    z[(size_t)r * DLAT + idxA] = 0.f;
    z[(size_t)r * DLAT + idxB] = rvB;
    g_topk_val[(size_t)r * K_TOP + (K_TOP - 1)] = rvB;
    g_topk_idx[(size_t)r * K_TOP + (K_TOP - 1)] = idxB;
}

// ---------------- sparse decode: x_hat, ghost_tgt, res_norm ----------------
__global__ void xhat_kernel(const float* __restrict__ x,
                            const float* __restrict__ b_dec,
                            const float* __restrict__ b_pre,
                            float* __restrict__ out_xhat,
                            float* __restrict__ out_tgt) {
    const int row = blockIdx.x;
    const int tid = threadIdx.x;
    __shared__ float sval[K_TOP];
    __shared__ int   sidx[K_TOP];
    __shared__ float red[256];

    if (tid < K_TOP) {
        sval[tid] = g_topk_val[(size_t)row * K_TOP + tid];
        sidx[tid] = g_topk_idx[(size_t)row * K_TOP + tid];
    }
    __syncthreads();

    float acc[16];
#pragma unroll
    for (int i = 0; i < 16; i++) acc[i] = 0.f;

    for (int j = 0; j < K_TOP; j++) {
        float v = sval[j];
        if (v != 0.f) {
            const float* wr = g_WdecT + (size_t)sidx[j] * DIN;
#pragma unroll
            for (int i = 0; i < 16; i++) acc[i] += v * wr[tid + i * 256];
        }
    }

    float ss = 0.f;
#pragma unroll
    for (int i = 0; i < 16; i++) {
        int d = tid + i * 256;
        float xh = acc[i] + b_dec[d] + b_pre[d];
        float r = x[(size_t)row * DIN + d] - xh;
        out_xhat[(size_t)row * DIN + d] = xh;
        out_tgt[(size_t)row * DIN + d] = 0.5f * r;
        ss += r * r;
    }
    red[tid] = ss;
    __syncthreads();
    for (int s = 128; s > 0; s >>= 1) {
        if (tid < s) red[tid] += red[tid + s];
        __syncthreads();
    }
    if (tid == 0) g_resnorm[row] = sqrtf(red[0]);
}

// ---------------- ghost row normalize+scale in place ----------------
__global__ void ghost_scale_kernel(float* __restrict__ ghost) {
    const int row = blockIdx.x;
    const int tid = threadIdx.x;
    __shared__ float red[256];
    __shared__ float s_scale;

    float v[16];
    float ss = 0.f;
#pragma unroll
    for (int i = 0; i < 16; i++) {
        v[i] = ghost[(size_t)row * DIN + tid + i * 256];
        ss += v[i] * v[i];
    }
    red[tid] = ss;
    __syncthreads();
    for (int s = 128; s > 0; s >>= 1) {
        if (tid < s) red[tid] += red[tid + s];
        __syncthreads();
    }
    if (tid == 0) {
        float gn = sqrtf(red[0]);
        s_scale = (gn > 1e-30f) ? (0.5f * g_resnorm[row] / gn) : 0.f;
    }
    __syncthreads();
    float sc = s_scale;
#pragma unroll
    for (int i = 0; i < 16; i++)
        ghost[(size_t)row * DIN + tid + i * 256] = v[i] * sc;
}

// ---------------- n_dead reduction ----------------
__global__ void ndead_kernel(const int* __restrict__ ssf,
                             const int* __restrict__ thr,
                             float* __restrict__ out_nd) {
    const int tid = threadIdx.x;
    __shared__ int red[256];
    const int t = read_flexint(thr, 0);
    int c = 0;
    for (int i = tid; i < DLAT; i += 256) c += (read_flexint(ssf, i) >= t) ? 1 : 0;
    red[tid] = c;
    __syncthreads();
    for (int s = 128; s > 0; s >>= 1) {
        if (tid < s) red[tid] += red[tid + s];
        __syncthreads();
    }
    if (tid == 0) out_nd[0] = (float)red[0];
}

// ---------------- launch ----------------
extern "C" void kernel_launch(void* const* d_in, const int* in_sizes, int n_in,
                              void* d_out, int out_size) {
    const float* x     = (const float*)d_in[0];
    const float* W_enc = (const float*)d_in[1];
    const float* b_enc = (const float*)d_in[2];
    const float* W_dec = (const float*)d_in[3];
    const float* b_dec = (const float*)d_in[4];
    const float* b_pre = (const float*)d_in[5];
    const int*   ssf   = (const int*)d_in[6];
    const int*   thr   = (const int*)d_in[7];

    float* out_pre   = (float*)d_out;
    float* out_z     = out_pre   + (size_t)NROWS * DLAT;
    float* out_xhat  = out_z     + (size_t)NROWS * DLAT;
    float* out_ghost = out_xhat  + (size_t)NROWS * DIN;
    float* out_tgt   = out_ghost + (size_t)NROWS * DIN;
    float* out_nd    = out_tgt   + (size_t)NROWS * DIN;

    void *p_xc, *p_we, *p_wd, *p_e;
    cudaGetSymbolAddress(&p_xc, g_xc);
    cudaGetSymbolAddress(&p_we, g_we);
    cudaGetSymbolAddress(&p_wd, g_wd);
    cudaGetSymbolAddress(&p_e,  g_E);

    cudaFuncSetAttribute(topcand_kernel, cudaFuncAttributeMaxDynamicSharedMemorySize,
                         DLAT * (int)sizeof(unsigned int));
    cudaFuncSetAttribute(gemm_fp16<0>, cudaFuncAttributeMaxDynamicSharedMemorySize, GEMM_SMEM);
    cudaFuncSetAttribute(gemm_fp16<1>, cudaFuncAttributeMaxDynamicSharedMemorySize, GEMM_SMEM);

    // 0) dead-column index list (padded to 64)
    build_dead_kernel<<<1, 1024>>>(ssf, thr);

    // 1) operand prep -> tiled+swizzled fp16
    transpose_wdec_kernel<<<dim3(DLAT / 32, DIN / 32), dim3(32, 8)>>>(W_dec);
    prep_x_kernel<<<(NROWS * DIN / 4) / 256, 256>>>(x, b_pre);
    conv_tiled_kernel<<<((size_t)DLAT * DIN / 4 + 255) / 256, 256>>>(
        W_enc, (__half*)p_we, DIN, (size_t)DLAT * DIN / 4);
    compact_wd_kernel<<<dim3(DLAT / 256, DIN), 256>>>(W_dec);

    // 2) encoder GEMM: pre = xc @ W_enc^T + b_enc
    gemm_fp16<0><<<(NROWS / 128) * (DLAT / 128), 256, GEMM_SMEM>>>(
        (const __half*)p_xc, (const __half*)p_we, out_pre, b_enc, NROWS, DLAT, DIN);

    // 3..5) top-96 -> exact refine -> exact select -> min-gap swap
    topcand_kernel<<<NROWS, 256, DLAT * sizeof(unsigned int)>>>(out_pre, out_z);
    refine_kernel<<<NROWS, 256>>>(x, W_enc, b_enc, b_pre);
    select_kernel<<<NROWS, 128>>>(out_z);
    argmin_gap_kernel<<<1, 256>>>();
    swap_fixup_kernel<<<1, 32>>>(out_z);

    // 6) sparse decode
    xhat_kernel<<<NROWS, 256>>>(x, b_dec, b_pre, out_xhat, out_tgt);

    // 7) masked exp (compacted, tiled+swizzled fp16)
    e_half_kernel<<<dim3(DLAT / 256, NROWS), 256>>>(out_pre);

    // 8) ghost GEMM over compacted K (reads g_Kc device-side)
    gemm_fp16<1><<<(NROWS / 128) * (DIN / 128), 256, GEMM_SMEM>>>(
        (const __half*)p_e, (const __half*)p_wd, out_ghost, nullptr, NROWS, DIN, 0);

    // 9) ghost normalize+scale
    ghost_scale_kernel<<<NROWS, 256>>>(out_ghost);

    // 10) n_dead
    ndead_kernel<<<1, 256>>>(ssf, thr, out_nd);
}

// round 16
// speedup vs baseline: 1.2536x; 1.0784x over previous
#include <cuda_runtime.h>
#include <cuda_fp16.h>
#include <math.h>
#include <stdint.h>

#define NROWS 4096
#define DIN   4096
#define DLAT  32768
#define K_TOP 64
#define NCAND 96

__device__ __forceinline__ int read_flexint(const int* p, int i) {
    int v = p[i];
    if ((unsigned)v > (1u << 20)) v = (int)__int_as_float(v);
    return v;
}

// ---------------- scratch (device globals; no allocations allowed) ----------------
__device__ float  g_WdecT[(size_t)DLAT * DIN];      // W_dec^T fp32 (xhat gathers)
__device__ __half g_xc[(size_t)NROWS * DIN];        // (x-b_pre) fp16, TILED+SW128
__device__ __half g_we[(size_t)DLAT * DIN];         // W_enc fp16, TILED+SW128
__device__ __half g_wd[(size_t)DIN * DLAT];         // W_dec fp16, compacted, TILED+SW128 (Kt=g_Kc)
__device__ __half g_E[(size_t)NROWS * DLAT];        // masked exp fp16, compacted, TILED+SW128
__device__ int    g_dead_idx[DLAT];
__device__ int    g_Kc;                             // padded dead count (mult of 64)
__device__ float  g_topk_val[(size_t)NROWS * K_TOP];
__device__ int    g_topk_idx[(size_t)NROWS * K_TOP];
__device__ int    g_cand[(size_t)NROWS * NCAND];
__device__ float  g_cval[(size_t)NROWS * NCAND];
__device__ float  g_resnorm[NROWS];
__device__ float  g_bval[NROWS * 2];
__device__ int    g_bidx[NROWS * 2];
__device__ int    g_swaprow;

// Tiled+swizzled element offset: tiles of 128 rows x 64 k (16KB), contiguous.
__device__ __forceinline__ size_t tiled_off(int row, int k, int Kt) {
    return ((size_t)(row >> 7) * (Kt >> 6) + (k >> 6)) * 8192
         + (size_t)((row & 127) * 64 + ((((k & 63) >> 3) ^ (row & 7)) << 3) + (k & 7));
}

// ---------------- W_dec transpose (fp32, for sparse decode) ----------------
__global__ void transpose_wdec_kernel(const float* __restrict__ wdec) {
    __shared__ float t[32][33];
    int bx = blockIdx.x * 32, by = blockIdx.y * 32;
    int x = threadIdx.x, y0 = threadIdx.y;
#pragma unroll
    for (int dy = 0; dy < 32; dy += 8)
        t[y0 + dy][x] = wdec[(size_t)(by + y0 + dy) * DLAT + bx + x];
    __syncthreads();
#pragma unroll
    for (int dy = 0; dy < 32; dy += 8)
        g_WdecT[(size_t)(bx + y0 + dy) * DIN + by + x] = t[x][y0 + dy];
}

// ---------------- fp32 -> fp16 into tiled+swizzled layout ----------------
__global__ void conv_tiled_kernel(const float* __restrict__ in, __half* __restrict__ out,
                                  int Kt, size_t n4) {
    size_t i = (size_t)blockIdx.x * blockDim.x + threadIdx.x;
    if (i >= n4) return;
    int row = (int)(i / (Kt / 4));
    int k0  = (int)(i % (Kt / 4)) * 4;
    float4 v = ((const float4*)in)[i];
    __half2 h0, h1;
    h0.x = __float2half_rn(v.x); h0.y = __float2half_rn(v.y);
    h1.x = __float2half_rn(v.z); h1.y = __float2half_rn(v.w);
    size_t o = tiled_off(row, k0, Kt);
    *(__half2*)(out + o)     = h0;
    *(__half2*)(out + o + 2) = h1;
}

__global__ void prep_x_kernel(const float* __restrict__ x, const float* __restrict__ b_pre) {
    size_t i = (size_t)blockIdx.x * blockDim.x + threadIdx.x;
    int row = (int)(i / (DIN / 4));
    int k0  = (int)(i % (DIN / 4)) * 4;
    float4 v = ((const float4*)x)[i];
    float4 bp = ((const float4*)b_pre)[k0 >> 2];
    __half2 h0, h1;
    h0.x = __float2half_rn(v.x - bp.x); h0.y = __float2half_rn(v.y - bp.y);
    h1.x = __float2half_rn(v.z - bp.z); h1.y = __float2half_rn(v.w - bp.w);
    size_t o = tiled_off(row, k0, DIN);
    *(__half2*)(g_xc + o)     = h0;
    *(__half2*)(g_xc + o + 2) = h1;
}

// ---------------- dead-column index build (+ n_dead output) ----------------
__global__ void build_dead_kernel(const int* __restrict__ ssf, const int* __restrict__ thr,
                                  float* __restrict__ out_nd) {
    __shared__ int scan[1024];
    __shared__ int base;
    const int tid = threadIdx.x;
    if (tid == 0) base = 0;
    __syncthreads();
    const int t = read_flexint(thr, 0);
    for (int c = 0; c < DLAT; c += 1024) {
        int f = (read_flexint(ssf, c + tid) >= t) ? 1 : 0;
        scan[tid] = f;
        __syncthreads();
        for (int s = 1; s < 1024; s <<= 1) {
            int v = (tid >= s) ? scan[tid - s] : 0;
            __syncthreads();
            scan[tid] += v;
            __syncthreads();
        }
        if (f) g_dead_idx[base + scan[tid] - 1] = c + tid;
        __syncthreads();
        if (tid == 1023) base += scan[1023];
        __syncthreads();
    }
    if (tid == 0) {
        int nd = base;
        int pad = (nd + 63) & ~63;
        for (int j = nd; j < pad; j++) g_dead_idx[j] = -1;
        g_Kc = pad;
        out_nd[0] = (float)nd;
    }
}

__global__ void compact_wd_kernel(const float* __restrict__ wdec) {
    const int Kc = g_Kc;
    int j = blockIdx.x * 256 + threadIdx.x;
    if (j >= Kc) return;
    int n = blockIdx.y;
    int src = g_dead_idx[j];
    float v = (src >= 0) ? wdec[(size_t)n * DLAT + src] : 0.f;
    g_wd[tiled_off(n, j, Kc)] = __float2half_rn(v);
}

__global__ void e_half_kernel(const float* __restrict__ pre) {
    const int Kc = g_Kc;
    int j = blockIdx.x * 256 + threadIdx.x;
    if (j >= Kc) return;
    int row = blockIdx.y;
    int src = g_dead_idx[j];
    float v = (src >= 0) ? expf(pre[(size_t)row * DLAT + src]) : 0.f;
    g_E[tiled_off(row, j, Kc)] = __float2half_rn(v);
}

// ==== fp16 GEMM: mma.sync + ldmatrix(SW128) + cp.async.bulk, 3-stage mbarrier ring ====
#define TILE_BYTES 16384
#define STAGE_BYTES (2 * TILE_BYTES)
#define NSTAGE 3
#define GEMM_SMEM (1024 + NSTAGE * STAGE_BYTES)

__device__ __forceinline__ void mma16816(float acc[4], const uint32_t a[4], const uint32_t b[2]) {
    asm volatile(
        "mma.sync.aligned.m16n8k16.row.col.f32.f16.f16.f32 "
        "{%0,%1,%2,%3}, {%4,%5,%6,%7}, {%8,%9}, {%0,%1,%2,%3};\n"
        : "+f"(acc[0]), "+f"(acc[1]), "+f"(acc[2]), "+f"(acc[3])
        : "r"(a[0]), "r"(a[1]), "r"(a[2]), "r"(a[3]), "r"(b[0]), "r"(b[1]));
}

__device__ __forceinline__ void ldsm_x4(uint32_t r[4], uint32_t saddr) {
    asm volatile("ldmatrix.sync.aligned.m8n8.x4.shared.b16 {%0,%1,%2,%3}, [%4];"
                 : "=r"(r[0]), "=r"(r[1]), "=r"(r[2]), "=r"(r[3]) : "r"(saddr));
}

__device__ __forceinline__ void mbar_init(uint32_t mbar, uint32_t cnt) {
    asm volatile("mbarrier.init.shared.b64 [%0], %1;" :: "r"(mbar), "r"(cnt) : "memory");
}

__device__ __forceinline__ void mbar_expect_tx(uint32_t mbar, uint32_t bytes) {
    asm volatile("mbarrier.arrive.expect_tx.shared.b64 _, [%0], %1;"
                 :: "r"(mbar), "r"(bytes) : "memory");
}

__device__ __forceinline__ void bulk_g2s(uint32_t sdst, const void* gsrc, uint32_t bytes,
                                         uint32_t mbar) {
    asm volatile(
        "cp.async.bulk.shared::cta.global.mbarrier::complete_tx::bytes [%0], [%1], %2, [%3];"
        :: "r"(sdst), "l"(gsrc), "r"(bytes), "r"(mbar) : "memory");
}

__device__ __forceinline__ void mbar_wait(uint32_t mbar, uint32_t parity) {
    uint32_t done = 0;
    while (!done) {
        asm volatile(
            "{\n\t.reg .pred p;\n\t"
            "mbarrier.try_wait.parity.acquire.cta.shared::cta.b64 p, [%1], %2, 0x989680;\n\t"
            "selp.b32 %0, 1, 0, p;\n\t}"
            : "=r"(done) : "r"(mbar), "r"(parity) : "memory");
    }
}

template <int MODE>   // 0: encoder (+bias, K=param), 1: ghost (plain, K=g_Kc)
__global__ __launch_bounds__(256, 2)
void gemm_fp16(const __half* __restrict__ A, const __half* __restrict__ B,
               float* __restrict__ C, const float* __restrict__ biasn,
               int M, int N, int Kparam) {
    extern __shared__ uint32_t sm[];
    const int tid = threadIdx.x;
    const int wid = tid >> 5, lane = tid & 31;
    const int K = (MODE == 1) ? g_Kc : Kparam;
    const int nk = K >> 6;

    const int num_m = M >> 7, num_n = N >> 7;
    int pid = blockIdx.x;
    const int ppg = 8 * num_n;
    int first_m = (pid / ppg) * 8;
    int gsz = num_m - first_m; if (gsz > 8) gsz = 8;
    int pin = pid % ppg;
    const int tm = first_m + (pin % gsz);
    const int tn = pin / gsz;
    const int bm = tm << 7, bn = tn << 7;

    const uint32_t smem_base = (uint32_t)__cvta_generic_to_shared(sm);
    const uint32_t mb = smem_base;
    const uint32_t sdata = smem_base + 1024;

    if (tid == 0) { mbar_init(mb, 1); mbar_init(mb + 8, 1); mbar_init(mb + 16, 1); }
    __syncthreads();

    const size_t a_tile0 = (size_t)tm * nk;
    const size_t b_tile0 = (size_t)tn * nk;

    const int wm = wid & 1, wn = wid >> 1;

    float acc[4][4][4];
#pragma unroll
    for (int i = 0; i < 4; i++)
#pragma unroll
        for (int j = 0; j < 4; j++)
#pragma unroll
            for (int q = 0; q < 4; q++) acc[i][j][q] = 0.f;

#define ISSUE_KT(kt_) do {                                                          \
        uint32_t s_ = sdata + (uint32_t)((kt_) % NSTAGE) * STAGE_BYTES;             \
        uint32_t m_ = mb + (uint32_t)((kt_) % NSTAGE) * 8;                          \
        mbar_expect_tx(m_, STAGE_BYTES);                                            \
        bulk_g2s(s_,              A + (a_tile0 + (kt_)) * 8192, TILE_BYTES, m_);    \
        bulk_g2s(s_ + TILE_BYTES, B + (b_tile0 + (kt_)) * 8192, TILE_BYTES, m_);    \
    } while (0)

    if (tid == 0) {
        ISSUE_KT(0);
        if (nk > 1) ISSUE_KT(1);
    }

    const int t8 = lane & 7, mid = lane >> 3;
    const int rsel = t8 + (mid & 1) * 8;
    const int csel = mid >> 1;

    for (int kt = 0; kt < nk; kt++) {
        mbar_wait(mb + (uint32_t)(kt % NSTAGE) * 8, (kt / NSTAGE) & 1);
        __syncthreads();
        if (tid == 0 && kt + 2 < nk) ISSUE_KT(kt + 2);

        const uint32_t stgA = sdata + (uint32_t)(kt % NSTAGE) * STAGE_BYTES;
        const uint32_t stgB = stgA + TILE_BYTES;
#pragma unroll
        for (int ks = 0; ks < 4; ks++) {
            uint32_t af[4][4], bf[4][2];
#pragma unroll
            for (int i = 0; i < 4; i++) {
                int ar = (wm * 4 + i) * 16 + rsel;
                ldsm_x4(af[i], stgA + (uint32_t)(ar * 128 + (((2 * ks + csel) ^ (ar & 7)) << 4)));
            }
#pragma unroll
            for (int jp = 0; jp < 2; jp++) {
                int br = wn * 32 + jp * 16 + rsel;
                uint32_t r[4];
                ldsm_x4(r, stgB + (uint32_t)(br * 128 + (((2 * ks + csel) ^ (br & 7)) << 4)));
                bf[2 * jp][0] = r[0]; bf[2 * jp + 1][0] = r[1];
                bf[2 * jp][1] = r[2]; bf[2 * jp + 1][1] = r[3];
            }
#pragma unroll
            for (int i = 0; i < 4; i++)
#pragma unroll
                for (int j = 0; j < 4; j++) mma16816(acc[i][j], af[i], bf[j]);
        }
    }

#pragma unroll
    for (int i = 0; i < 4; i++) {
        int row = bm + wm * 64 + i * 16 + (lane >> 2);
#pragma unroll
        for (int j = 0; j < 4; j++) {
            int col = bn + wn * 32 + j * 8 + ((lane & 3) << 1);
            float b0 = 0.f, b1 = 0.f;
            if (MODE == 0) { b0 = biasn[col]; b1 = biasn[col + 1]; }
            *(float2*)&C[(size_t)row * N + col] = make_float2(acc[i][j][0] + b0, acc[i][j][1] + b1);
            *(float2*)&C[(size_t)(row + 8) * N + col] = make_float2(acc[i][j][2] + b0, acc[i][j][3] + b1);
        }
    }
#undef ISSUE_KT
}

// ---------------- per-row top-NCAND candidate radix select (fp32) ----------------
__global__ void topcand_kernel(const float* __restrict__ pre, float* __restrict__ z) {
    extern __shared__ unsigned int skeys[];
    __shared__ unsigned int hist[256];
    __shared__ int s_digit, s_kk, s_cnt, s_eqcnt;
    __shared__ int eqbuf[128];

    const int row = blockIdx.x;
    const int tid = threadIdx.x;
    const float* prow = pre + (size_t)row * DLAT;

    for (int i = tid; i < DLAT; i += 256) {
        unsigned int u = __float_as_uint(prow[i]);
        u = (u & 0x80000000u) ? ~u : (u | 0x80000000u);
        skeys[i] = u;
    }
    if (tid == 0) s_kk = NCAND;
    __syncthreads();

    unsigned int pref = 0, pmask = 0;
    for (int r = 0; r < 4; r++) {
        const int shift = 24 - 8 * r;
        hist[tid] = 0u;
        __syncthreads();
        for (int i = tid; i < DLAT; i += 256) {
            unsigned int u = skeys[i];
            if ((u & pmask) == pref) atomicAdd(&hist[(u >> shift) & 255u], 1u);
        }
        __syncthreads();
        if (tid == 0) {
            int kk = s_kk; unsigned int cum = 0; int d = 0;
            for (int dig = 255; dig >= 0; dig--) {
                unsigned int h = hist[dig];
                if (cum + h >= (unsigned)kk) { d = dig; s_kk = kk - (int)cum; break; }
                cum += h;
            }
            s_digit = d;
        }
        __syncthreads();
        pref  |= ((unsigned)s_digit) << shift;
        pmask |= 0xffu << shift;
        __syncthreads();
    }
    const unsigned int T = pref;

    if (tid == 0) { s_cnt = 0; s_eqcnt = 0; }
    float* zrow = z + (size_t)row * DLAT;
    for (int i = tid; i < DLAT; i += 256) zrow[i] = 0.f;
    __syncthreads();

    for (int i = tid; i < DLAT; i += 256) {
        unsigned int u = skeys[i];
        if (u > T) {
            int p = atomicAdd(&s_cnt, 1);
            g_cand[(size_t)row * NCAND + p] = i;
        } else if (u == T) {
            int p = atomicAdd(&s_eqcnt, 1);
            if (p < 128) eqbuf[p] = i;
        }
    }
    __syncthreads();
    if (tid == 0) {
        int rem = NCAND - s_cnt;
        int ec = s_eqcnt < 128 ? s_eqcnt : 128;
        for (int t = 0; t < rem; t++) {
            int mi = -1, mv = 0x7fffffff;
            for (int q = 0; q < ec; q++)
                if (eqbuf[q] < mv) { mv = eqbuf[q]; mi = q; }
            if (mi < 0) break;
            eqbuf[mi] = 0x7fffffff;
            g_cand[(size_t)row * NCAND + s_cnt + t] = mv;
        }
    }
}

// ---------------- exact fp64 refinement ----------------
__global__ __launch_bounds__(256)
void refine_kernel(const float* __restrict__ x,
                   const float* __restrict__ W_enc,
                   const float* __restrict__ b_enc,
                   const float* __restrict__ b_pre) {
    const int row  = blockIdx.x;
    const int tid  = threadIdx.x;
    const int wid  = tid >> 5;
    const int lane = tid & 31;
    __shared__ float sx[DIN];

    for (int i = tid; i < DIN; i += 256)
        sx[i] = x[(size_t)row * DIN + i] - b_pre[i];
    __syncthreads();

    for (int c_i = wid; c_i < NCAND; c_i += 8) {
        const int c = g_cand[(size_t)row * NCAND + c_i];
        const float* wr = W_enc + (size_t)c * DIN;
        double a0 = 0.0, a1 = 0.0, a2 = 0.0, a3 = 0.0;
#pragma unroll 8
        for (int j = 0; j < DIN / 32; j += 4) {
            a0 += (double)sx[lane + (j + 0) * 32] * (double)wr[lane + (j + 0) * 32];
            a1 += (double)sx[lane + (j + 1) * 32] * (double)wr[lane + (j + 1) * 32];
            a2 += (double)sx[lane + (j + 2) * 32] * (double)wr[lane + (j + 2) * 32];
            a3 += (double)sx[lane + (j + 3) * 32] * (double)wr[lane + (j + 3) * 32];
        }
        double acc = (a0 + a1) + (a2 + a3);
#pragma unroll
        for (int off = 16; off > 0; off >>= 1)
            acc += __shfl_xor_sync(0xffffffffu, acc, off);
        if (lane == 0)
            g_cval[(size_t)row * NCAND + c_i] = (float)(acc + (double)b_enc[c]);
    }
}

// ---------------- exact ranking + boundary record ----------------
__global__ void select_kernel(float* __restrict__ z) {
    const int row = blockIdx.x;
    const int tid = threadIdx.x;
    __shared__ float sv[NCAND];
    __shared__ int   si[NCAND];

    if (tid < NCAND) {
        sv[tid] = g_cval[(size_t)row * NCAND + tid];
        si[tid] = g_cand[(size_t)row * NCAND + tid];
    }
    __syncthreads();

    if (tid < NCAND) {
        float v = sv[tid];
        int   ix = si[tid];
        int rank = 0;
#pragma unroll 8
        for (int q = 0; q < NCAND; q++) {
            float vq = sv[q];
            rank += (vq > v) || (vq == v && si[q] < ix);
        }
        if (rank < K_TOP) {
            float rv = fmaxf(v, 0.f);
            z[(size_t)row * DLAT + ix] = rv;
            g_topk_val[(size_t)row * K_TOP + rank] = rv;
            g_topk_idx[(size_t)row * K_TOP + rank] = ix;
        }
        if (rank == K_TOP - 1)  { g_bval[row * 2 + 0] = v; g_bidx[row * 2 + 0] = ix; }
        else if (rank == K_TOP) { g_bval[row * 2 + 1] = v; g_bidx[row * 2 + 1] = ix; }
    }
}

__global__ void argmin_gap_kernel() {
    const int tid = threadIdx.x;
    __shared__ float rv[256];
    __shared__ int   ri[256];
    float best = 1e30f; int bestr = 0;
    for (int r = tid; r < NROWS; r += 256) {
        float g = g_bval[r * 2 + 0] - g_bval[r * 2 + 1];
        if (g < best) { best = g; bestr = r; }
    }
    rv[tid] = best; ri[tid] = bestr;
    __syncthreads();
    for (int s = 128; s > 0; s >>= 1) {
        if (tid < s && rv[tid + s] < rv[tid]) { rv[tid] = rv[tid + s]; ri[tid] = ri[tid + s]; }
        __syncthreads();
    }
    if (tid == 0) g_swaprow = ri[0];
}

__global__ void swap_fixup_kernel(float* __restrict__ z) {
    if (threadIdx.x != 0) return;
    const int r = g_swaprow;
    const int idxA = g_bidx[r * 2 + 0];
    const int idxB = g_bidx[r * 2 + 1];
    const float rvB = fmaxf(g_bval[r * 2 + 1], 0.f);
    z[(size_t)r * DLAT + idxA] = 0.f;
    z[(size_t)r * DLAT + idxB] = rvB;
    g_topk_val[(size_t)r * K_TOP + (K_TOP - 1)] = rvB;
    g_topk_idx[(size_t)r * K_TOP + (K_TOP - 1)] = idxB;
}

// ---------------- sparse decode: x_hat, ghost_tgt, res_norm ----------------
__global__ void xhat_kernel(const float* __restrict__ x,
                            const float* __restrict__ b_dec,
                            const float* __restrict__ b_pre,
                            float* __restrict__ out_xhat,
                            float* __restrict__ out_tgt) {
    const int row = blockIdx.x;
    const int tid = threadIdx.x;
    __shared__ float sval[K_TOP];
    __shared__ int   sidx[K_TOP];
    __shared__ float red[256];

    if (tid < K_TOP) {
        sval[tid] = g_topk_val[(size_t)row * K_TOP + tid];
        sidx[tid] = g_topk_idx[(size_t)row * K_TOP + tid];
    }
    __syncthreads();

    float acc[16];
#pragma unroll
    for (int i = 0; i < 16; i++) acc[i] = 0.f;

    for (int j = 0; j < K_TOP; j++) {
        float v = sval[j];
        if (v != 0.f) {
            const float* wr = g_WdecT + (size_t)sidx[j] * DIN;
#pragma unroll
            for (int i = 0; i < 16; i++) acc[i] += v * wr[tid + i * 256];
        }
    }

    float ss = 0.f;
#pragma unroll
    for (int i = 0; i < 16; i++) {
        int d = tid + i * 256;
        float xh = acc[i] + b_dec[d] + b_pre[d];
        float r = x[(size_t)row * DIN + d] - xh;
        out_xhat[(size_t)row * DIN + d] = xh;
        out_tgt[(size_t)row * DIN + d] = 0.5f * r;
        ss += r * r;
    }
    red[tid] = ss;
    __syncthreads();
    for (int s = 128; s > 0; s >>= 1) {
        if (tid < s) red[tid] += red[tid + s];
        __syncthreads();
    }
    if (tid == 0) g_resnorm[row] = sqrtf(red[0]);
}

// ---------------- ghost row normalize+scale in place ----------------
__global__ void ghost_scale_kernel(float* __restrict__ ghost) {
    const int row = blockIdx.x;
    const int tid = threadIdx.x;
    __shared__ float red[256];
    __shared__ float s_scale;

    float v[16];
    float ss = 0.f;
#pragma unroll
    for (int i = 0; i < 16; i++) {
        v[i] = ghost[(size_t)row * DIN + tid + i * 256];
        ss += v[i] * v[i];
    }
    red[tid] = ss;
    __syncthreads();
    for (int s = 128; s > 0; s >>= 1) {
        if (tid < s) red[tid] += red[tid + s];
        __syncthreads();
    }
    if (tid == 0) {
        float gn = sqrtf(red[0]);
        s_scale = (gn > 1e-30f) ? (0.5f * g_resnorm[row] / gn) : 0.f;
    }
    __syncthreads();
    float sc = s_scale;
#pragma unroll
    for (int i = 0; i < 16; i++)
        ghost[(size_t)row * DIN + tid + i * 256] = v[i] * sc;
}

// ---------------- launch (dual-stream overlap, capture-legal fork/join) ----------------
extern "C" void kernel_launch(void* const* d_in, const int* in_sizes, int n_in,
                              void* d_out, int out_size) {
    const float* x     = (const float*)d_in[0];
    const float* W_enc = (const float*)d_in[1];
    const float* b_enc = (const float*)d_in[2];
    const float* W_dec = (const float*)d_in[3];
    const float* b_dec = (const float*)d_in[4];
    const float* b_pre = (const float*)d_in[5];
    const int*   ssf   = (const int*)d_in[6];
    const int*   thr   = (const int*)d_in[7];

    float* out_pre   = (float*)d_out;
    float* out_z     = out_pre   + (size_t)NROWS * DLAT;
    float* out_xhat  = out_z     + (size_t)NROWS * DLAT;
    float* out_ghost = out_xhat  + (size_t)NROWS * DIN;
    float* out_tgt   = out_ghost + (size_t)NROWS * DIN;
    float* out_nd    = out_tgt   + (size_t)NROWS * DIN;

    void *p_xc, *p_we, *p_wd, *p_e;
    cudaGetSymbolAddress(&p_xc, g_xc);
    cudaGetSymbolAddress(&p_we, g_we);
    cudaGetSymbolAddress(&p_wd, g_wd);
    cudaGetSymbolAddress(&p_e,  g_E);

    cudaFuncSetAttribute(topcand_kernel, cudaFuncAttributeMaxDynamicSharedMemorySize,
                         DLAT * (int)sizeof(unsigned int));
    cudaFuncSetAttribute(gemm_fp16<0>, cudaFuncAttributeMaxDynamicSharedMemorySize, GEMM_SMEM);
    cudaFuncSetAttribute(gemm_fp16<1>, cudaFuncAttributeMaxDynamicSharedMemorySize, GEMM_SMEM);

    // side stream + events (host objects; no device memory)
    cudaStream_t sB;
    cudaStreamCreateWithFlags(&sB, cudaStreamNonBlocking);
    cudaEvent_t evRoot, evEnc, evPrepB, evGhost;
    cudaEventCreateWithFlags(&evRoot,  cudaEventDisableTiming);
    cudaEventCreateWithFlags(&evEnc,   cudaEventDisableTiming);
    cudaEventCreateWithFlags(&evPrepB, cudaEventDisableTiming);
    cudaEventCreateWithFlags(&evGhost, cudaEventDisableTiming);

    // FORK: join sB into the capture BEFORE any work lands on it.
    cudaEventRecord(evRoot, 0);
    cudaStreamWaitEvent(sB, evRoot, 0);

    // ---- stream B: W_dec prep (independent of encoder) ----
    build_dead_kernel<<<1, 1024, 0, sB>>>(ssf, thr, out_nd);
    transpose_wdec_kernel<<<dim3(DLAT / 32, DIN / 32), dim3(32, 8), 0, sB>>>(W_dec);
    compact_wd_kernel<<<dim3(DLAT / 256, DIN), 256, 0, sB>>>(W_dec);
    cudaEventRecord(evPrepB, sB);

    // ---- main stream: encoder prep + encoder GEMM ----
    prep_x_kernel<<<(NROWS * DIN / 4) / 256, 256>>>(x, b_pre);
    conv_tiled_kernel<<<((size_t)DLAT * DIN / 4 + 255) / 256, 256>>>(
        W_enc, (__half*)p_we, DIN, (size_t)DLAT * DIN / 4);
    gemm_fp16<0><<<(NROWS / 128) * (DLAT / 128), 256, GEMM_SMEM>>>(
        (const __half*)p_xc, (const __half*)p_we, out_pre, b_enc, NROWS, DLAT, DIN);
    cudaEventRecord(evEnc, 0);

    // ---- stream B: ghost pipeline (needs pre + dead prep) ----
    cudaStreamWaitEvent(sB, evEnc, 0);
    e_half_kernel<<<dim3(DLAT / 256, NROWS), 256, 0, sB>>>(out_pre);
    gemm_fp16<1><<<(NROWS / 128) * (DIN / 128), 256, GEMM_SMEM, sB>>>(
        (const __half*)p_e, (const __half*)p_wd, out_ghost, nullptr, NROWS, DIN, 0);
    cudaEventRecord(evGhost, sB);

    // ---- main stream (concurrent with ghost): topk chain ----
    topcand_kernel<<<NROWS, 256, DLAT * sizeof(unsigned int)>>>(out_pre, out_z);
    refine_kernel<<<NROWS, 256>>>(x, W_enc, b_enc, b_pre);
    select_kernel<<<NROWS, 128>>>(out_z);
    argmin_gap_kernel<<<1, 256>>>();
    swap_fixup_kernel<<<1, 32>>>(out_z);
    cudaStreamWaitEvent(0, evPrepB, 0);   // xhat reads g_WdecT
    xhat_kernel<<<NROWS, 256>>>(x, b_dec, b_pre, out_xhat, out_tgt);

    // ---- JOIN: ghost normalize+scale needs G (stream B) and resnorm (main) ----
    cudaStreamWaitEvent(0, evGhost, 0);
    ghost_scale_kernel<<<NROWS, 256>>>(out_ghost);
}